// round 15
// baseline (speedup 1.0000x reference)
#include <cuda_runtime.h>
#include <cuda_fp16.h>
#include <math.h>
#include <stdint.h>

#define B_  64
#define N_  512
#define D_  256
#define H_  8
#define DK_ 32
#define M_  (B_*N_)   // 32768

// Q pre-scale: (1/sqrt(DK)) * log2(e)  -> softmax done in exp2 domain
#define QSCALE 0.25502421277695494f

// ---------------- scratch (static device globals; no allocation) ----------
__device__ __align__(256) __half g_hh[M_*D_];     // h in fp16
__device__ __align__(256) __half g_qh[M_*D_];
__device__ __align__(256) __half g_kh[M_*D_];
__device__ __align__(256) __half g_vh[M_*D_];
__device__ __align__(256) __half g_aoh[M_*D_];    // attention output fp16
__device__ __align__(256) __half g_wt[4*D_*D_];   // fp16 W^T (n-major) x4
__device__ unsigned char g_inv[M_];
__device__ unsigned int  g_invbits[M_/32];

// ---------------- helpers ---------------------------------------------------
__device__ __forceinline__ uint32_t pack_h2(float lo, float hi) {
    uint32_t r;
    asm("cvt.rn.f16x2.f32 %0, %1, %2;" : "=r"(r) : "f"(hi), "f"(lo));
    return r;
}
__device__ __forceinline__ float ex2f(float x) {
    float r;
    asm("ex2.approx.f32 %0, %1;" : "=f"(r) : "f"(x));
    return r;
}
__device__ __forceinline__ uint32_t h2exp2(uint32_t x) {
    uint32_t r;
    asm("ex2.approx.f16x2 %0, %1;" : "=r"(r) : "r"(x));
    return r;
}
__device__ __forceinline__ void mma_f16(float* d, const uint32_t* a, const uint32_t* b) {
    asm volatile(
        "mma.sync.aligned.m16n8k16.row.col.f32.f16.f16.f32 "
        "{%0,%1,%2,%3}, {%4,%5,%6,%7}, {%8,%9}, {%0,%1,%2,%3};\n"
        : "+f"(d[0]), "+f"(d[1]), "+f"(d[2]), "+f"(d[3])
        : "r"(a[0]), "r"(a[1]), "r"(a[2]), "r"(a[3]), "r"(b[0]), "r"(b[1]));
}
__device__ __forceinline__ void ldsm_x4(uint32_t& r0, uint32_t& r1, uint32_t& r2,
                                        uint32_t& r3, uint32_t saddr) {
    asm volatile("ldmatrix.sync.aligned.m8n8.x4.shared.b16 {%0,%1,%2,%3}, [%4];"
                 : "=r"(r0), "=r"(r1), "=r"(r2), "=r"(r3) : "r"(saddr));
}
__device__ __forceinline__ void cpasync16(void* smem_dst, const void* gptr) {
    uint32_t d = (uint32_t)__cvta_generic_to_shared(smem_dst);
    asm volatile("cp.async.ca.shared.global [%0], [%1], 16;\n" :: "r"(d), "l"(gptr));
}

// ---------------- prep kernels ----------------------------------------------
__global__ void mask_kernel(const int* __restrict__ mask,
                            const int* __restrict__ ncount) {
    const int idx = blockIdx.x * 256 + threadIdx.x;
    if (idx < M_) {
        const int b = idx >> 9;
        const int n = idx & 511;
        const bool inv = (mask[2*idx] != 0) || (mask[2*idx+1] != 0) || (n >= ncount[b]);
        g_inv[idx] = inv ? 1 : 0;
        const unsigned bal = __ballot_sync(0xffffffffu, inv);
        if ((threadIdx.x & 31) == 0) g_invbits[idx >> 5] = bal;
    }
}

// h (f32) -> g_hh (fp16); one float4 per thread
__global__ void convh_kernel(const float* __restrict__ h) {
    const int idx = blockIdx.x * 256 + threadIdx.x;   // 0 .. M_*D_/4-1
    const float4 v = *(const float4*)&h[idx * 4];
    uint2 o;
    o.x = pack_h2(v.x, v.y);
    o.y = pack_h2(v.z, v.w);
    *(uint2*)&g_hh[idx * 4] = o;
}

// W (f32 [k][n]) -> g_wt (fp16 W^T [n][k]); 4 k-entries per thread
__global__ void convw_kernel(const float* __restrict__ Wq, const float* __restrict__ Wk,
                             const float* __restrict__ Wv, const float* __restrict__ Wo) {
    const int idx = blockIdx.x * 256 + threadIdx.x;   // 65536 threads
    const int m = idx >> 14;                          // matrix 0..3
    const int r = idx & 16383;
    const int n = r & 255;
    const int k0 = (r >> 8) * 4;
    const float* src = (m == 0) ? Wq : (m == 1) ? Wk : (m == 2) ? Wv : Wo;
    uint2 o;
    o.x = pack_h2(src[(k0+0)*D_ + n], src[(k0+1)*D_ + n]);
    o.y = pack_h2(src[(k0+2)*D_ + n], src[(k0+3)*D_ + n]);
    *(uint2*)&g_wt[m*D_*D_ + n*D_ + k0] = o;
}

// ---------------- fp16 mma GEMM, 64x64 warp tiles ----------------------------
// block 128x256 (full N), 256 threads / 8 warps in 2x4 grid, BK=32, 3 stages.
// Per k16: 4 A-ldsm.x4 + 4 B-ldsm.x4 -> 32 mma (0.25 ldsm/mma).
// OUT: 0 = f32 + bias + res (oproj), 2 = fp16 (acc+bias)*scale (Q/K/V)
#define HSTAGE_B 30720            // bytes/stage: A 128*40h (10240B) + B 256*40h (20480B)
#define GEMMH_SMEM_BYTES (3*HSTAGE_B)   // 92160

template<int OUT>
__device__ __forceinline__ void gemm_h(const __half* __restrict__ A,
                                       const __half* __restrict__ Wt,
                                       const float* __restrict__ bias,
                                       const float* __restrict__ res,
                                       float* __restrict__ Cf,
                                       __half* __restrict__ Ch,
                                       float scale) {
    extern __shared__ char smc[];
    const uint32_t sb = (uint32_t)__cvta_generic_to_shared(smc);

    const int tid  = threadIdx.x;
    const int lane = tid & 31, warp = tid >> 5;
    const int g = lane >> 2, t = lane & 3;
    const int lrow = lane & 7, grp = lane >> 3;
    const int mw = (warp >> 2) * 64;     // 2 m-warps
    const int nw = (warp & 3) * 64;      // 4 n-warps
    const int row0 = blockIdx.x * 128;

    const int ar = tid >> 2, ac = (tid & 3) * 8;   // loader: 64 rows x 32h per pass

    float acc[4][8][4];
#pragma unroll
    for (int i = 0; i < 4; i++)
#pragma unroll
        for (int j = 0; j < 8; j++)
#pragma unroll
            for (int q = 0; q < 4; q++) acc[i][j][q] = 0.f;

    const __half* gA = A  + (size_t)(row0 + ar)*D_ + ac;
    const __half* gB = Wt + (size_t)ar*D_ + ac;          // full N (256 rows of W^T)

    auto issue = [&](int chunk, int stage) {
        __half* As = (__half*)(smc + stage*HSTAGE_B);
        __half* Bs = As + 5120;
#pragma unroll
        for (int p = 0; p < 2; p++)
            cpasync16(&As[(ar + 64*p)*40 + ac], gA + (size_t)(64*p)*D_ + chunk*32);
#pragma unroll
        for (int p = 0; p < 4; p++)
            cpasync16(&Bs[(ar + 64*p)*40 + ac], gB + (size_t)(64*p)*D_ + chunk*32);
        asm volatile("cp.async.commit_group;\n" ::: "memory");
    };

    issue(0, 0);
    issue(1, 1);

    // ldmatrix bases (byte offsets), NON-trans (validated pattern):
    // A: rows (m) split on (grp&1)*8, k on (grp>>1)*8 -> {a0,a1,a2,a3}
    // B (=W^T): rows (n) on (grp>>1)*8, k on (grp&1)*8 -> {b0,b1} per octet
    const uint32_t a_base = sb
        + (uint32_t)(((mw + (grp&1)*8 + lrow)*40 + (grp>>1)*8) * 2);
    const uint32_t b_base = sb + 10240
        + (uint32_t)(((nw + (grp>>1)*8 + lrow)*40 + (grp&1)*8) * 2);

    for (int i = 0; i < 8; i++) {
        if (i < 7) asm volatile("cp.async.wait_group 1;\n" ::: "memory");
        else       asm volatile("cp.async.wait_group 0;\n" ::: "memory");
        __syncthreads();
        if (i < 6) issue(i + 2, (i + 2) % 3);

        const uint32_t st = (uint32_t)((i % 3) * HSTAGE_B);
#pragma unroll
        for (int kh = 0; kh < 2; kh++) {
            uint32_t aq[4][4];
#pragma unroll
            for (int mi = 0; mi < 4; mi++)
                ldsm_x4(aq[mi][0], aq[mi][1], aq[mi][2], aq[mi][3],
                        a_base + st + mi*1280 + kh*32);       // +16 rows * 80B
#pragma unroll
            for (int jb = 0; jb < 4; jb++) {
                uint32_t bf[4];
                ldsm_x4(bf[0], bf[1], bf[2], bf[3],
                        b_base + st + jb*1280 + kh*32);
#pragma unroll
                for (int mi = 0; mi < 4; mi++) {
                    mma_f16(acc[mi][jb*2+0], aq[mi], bf);
                    mma_f16(acc[mi][jb*2+1], aq[mi], bf + 2);
                }
            }
        }
        __syncthreads();
    }

#pragma unroll
    for (int mi = 0; mi < 4; mi++) {
        const int r0g = row0 + mw + mi*16 + g;
#pragma unroll
        for (int na = 0; na < 8; na++) {
            const int c0 = nw + na*8 + 2*t;
            float2 o0, o1;
            o0.x = acc[mi][na][0] + bias[c0];
            o0.y = acc[mi][na][1] + bias[c0+1];
            o1.x = acc[mi][na][2] + bias[c0];
            o1.y = acc[mi][na][3] + bias[c0+1];
            if (OUT == 2) {
                *(uint32_t*)&Ch[(size_t)r0g*D_ + c0]     = pack_h2(o0.x*scale, o0.y*scale);
                *(uint32_t*)&Ch[(size_t)(r0g+8)*D_ + c0] = pack_h2(o1.x*scale, o1.y*scale);
            } else {
                const float2 ra = *(const float2*)&res[(size_t)r0g*D_ + c0];
                const float2 rb = *(const float2*)&res[(size_t)(r0g+8)*D_ + c0];
                o0.x += ra.x; o0.y += ra.y;
                o1.x += rb.x; o1.y += rb.y;
                *(float2*)&Cf[(size_t)r0g*D_ + c0]     = o0;
                *(float2*)&Cf[(size_t)(r0g+8)*D_ + c0] = o1;
            }
        }
    }
}

__global__ void __launch_bounds__(256)
qkv_kernel(const float* __restrict__ bq, const float* __restrict__ bk,
           const float* __restrict__ bv) {
    const int z = blockIdx.z;   // 0=Q, 1=K, 2=V
    const float* bb = (z == 0) ? bq : (z == 1) ? bk : bv;
    __half* outp   = (z == 0) ? g_qh : (z == 1) ? g_kh : g_vh;
    gemm_h<2>(g_hh, g_wt + z*D_*D_, bb, nullptr, nullptr, outp,
              (z == 0) ? QSCALE : 1.0f);
}

__global__ void __launch_bounds__(256)
oproj_kernel(const float* __restrict__ bo,
             const float* __restrict__ hres, float* __restrict__ out) {
    gemm_h<0>(g_aoh, g_wt + 3*D_*D_, bo, hres, out, nullptr, 1.0f);
}

// ---------------- register-flash attention (validated R14) -------------------
// per-warp max + deferred rescale, ex2.f16x2 exp, ones-column row sums.
#define KH_STR  40                // halves per K/Q smem row (80 B, cf-free ldsm)
#define VT_STR  520               // halves per dk row of V^T
#define OFFB_K  0                 // Kh[512][40]h  = 40960 B
#define OFFB_VT 40960             // Vt[32][520]h  = 33280 B
#define OFFB_Q  74240             // Qh[64][40]h   = 5120 B
#define OFFB_OP 79360             // Op[16][16][40]f = 40960 B
#define OFFB_MR 120320            // Mred[64][4]f (per-warp maxes)
#define OFFB_SR 121344            // Sred[64][4]f (per-warp sums)
#define ATTN_SMEM_BYTES 122368

__global__ void __launch_bounds__(512)
attn_kernel() {
    extern __shared__ char smc[];
    __half* Qhs  = (__half*)(smc + OFFB_Q);
    __half* Khs  = (__half*)(smc + OFFB_K);
    __half* Vth  = (__half*)(smc + OFFB_VT);
    float*  Op   = (float*) (smc + OFFB_OP);
    float*  Mred = (float*) (smc + OFFB_MR);
    float*  Sred = (float*) (smc + OFFB_SR);
    const uint32_t sb = (uint32_t)__cvta_generic_to_shared(smc);

    const int tid  = threadIdx.x;
    const int lane = tid & 31;
    const int warp = tid >> 5;
    const int g = lane >> 2, t = lane & 3;
    const int lrow = lane & 7, grp = lane >> 3;
    const int ma   = warp >> 2;          // q-row atom 0..3
    const int kspl = warp & 3;           // key-split 0..3
    const int bh   = blockIdx.x >> 1;
    const int half = blockIdx.x & 1;
    const int b  = bh >> 3;
    const int hh = bh & 7;

    const __half* Qg  = g_qh  + (size_t)b*N_*D_ + hh*DK_;
    const __half* Kg  = g_kh  + (size_t)b*N_*D_ + hh*DK_;
    const __half* Vg  = g_vh  + (size_t)b*N_*D_ + hh*DK_;
    __half*       Ogh = g_aoh + (size_t)b*N_*D_ + hh*DK_;

    uint32_t invw[4];
#pragma unroll
    for (int j = 0; j < 4; j++)
        invw[j] = g_invbits[b*16 + kspl*4 + j] >> (t << 1);

    // ---- load K (fp16 row-major) and V (fp16 transposed) ----
    {
        const int r = tid >> 3, cg = (tid & 7) * 4;     // 4 halves per thread
#pragma unroll
        for (int p = 0; p < 8; p++) {
            const int key = r + 64*p;
            *(uint2*)&Khs[key*KH_STR + cg] = *(const uint2*)&Kg[(size_t)key*D_ + cg];
            const uint2 u = *(const uint2*)&Vg[(size_t)key*D_ + cg];
            const __half2 v01 = *reinterpret_cast<const __half2*>(&u.x);
            const __half2 v23 = *reinterpret_cast<const __half2*>(&u.y);
            Vth[(cg+0)*VT_STR + key] = __low2half(v01);
            Vth[(cg+1)*VT_STR + key] = __high2half(v01);
            Vth[(cg+2)*VT_STR + key] = __low2half(v23);
            Vth[(cg+3)*VT_STR + key] = __high2half(v23);
        }
    }

    const int kb0 = kspl * 128;
    const int rr0 = ma*16 + g;                   // row within 64-row tile
    const int rr04 = rr0 * 4;
    const uint32_t FULL = 0xffffffffu;
    // ones-column B-frag for row-sum mma: col 0 = 1.0, cols 1..7 = 0
    const uint32_t onesf = (g == 0) ? 0x3C003C00u : 0u;
    const uint32_t onesbf[2] = { onesf, onesf };

    const uint32_t qa_base = sb + OFFB_Q
        + (uint32_t)(((ma*16 + (grp&1)*8 + lrow)*KH_STR + (grp>>1)*8) * 2);
    const uint32_t ka_row  = (uint32_t)((grp>>1)*8 + lrow);
    const uint32_t ka_koff = (uint32_t)((grp&1)*8);

    for (int qt = 0; qt < 4; qt++) {
        const int q0 = half*256 + qt*64;

        // ---- stage Q tile 64x32 fp16 ----
        __syncthreads();     // prior combine done; Qs/Op/Mred/Sred free
        {
            const int r = tid >> 3, cg = (tid & 7) * 4;
            *(uint2*)&Qhs[r*KH_STR + cg] = *(const uint2*)&Qg[(size_t)(q0 + r)*D_ + cg];
        }
        __syncthreads();

        const bool iq0 = g_inv[b*N_ + q0 + rr0]     != 0;
        const bool iq1 = g_inv[b*N_ + q0 + rr0 + 8] != 0;

        // ---- phase 1: S[16 x 128] = Q @ K^T, fp16 m16n8k16 ----
        uint32_t aq[2][4];
        ldsm_x4(aq[0][0], aq[0][1], aq[0][2], aq[0][3], qa_base);
        ldsm_x4(aq[1][0], aq[1][1], aq[1][2], aq[1][3], qa_base + 32);

        float acc[16][4];
#pragma unroll
        for (int j = 0; j < 8; j++) {
            const uint32_t kaddr = sb + OFFB_K
                + (uint32_t)((((kb0 + j*16) + ka_row)*KH_STR + ka_koff) * 2);
            uint32_t kb[4], kc[4];
            ldsm_x4(kb[0], kb[1], kb[2], kb[3], kaddr);        // dk 0-15
            ldsm_x4(kc[0], kc[1], kc[2], kc[3], kaddr + 32);   // dk 16-31
            acc[2*j][0] = acc[2*j][1] = acc[2*j][2] = acc[2*j][3] = 0.f;
            acc[2*j+1][0] = acc[2*j+1][1] = acc[2*j+1][2] = acc[2*j+1][3] = 0.f;
            mma_f16(acc[2*j],   aq[0], kb);
            mma_f16(acc[2*j],   aq[1], kc);
            mma_f16(acc[2*j+1], aq[0], kb + 2);
            mma_f16(acc[2*j+1], aq[1], kc + 2);
        }

        // ---- mask (regs), per-warp row max (quad shuffles only) ----
        float mx0 = -1e30f, mx1 = -1e30f;
#pragma unroll
        for (int na = 0; na < 16; na++) {
            const uint32_t w = invw[na >> 2] >> ((na & 3) << 3);
            const bool ik0 = (w & 1u) != 0;
            const bool ik1 = (w & 2u) != 0;
            acc[na][0] = (iq0 || ik0) ? -1e9f : acc[na][0];
            acc[na][1] = (iq0 || ik1) ? -1e9f : acc[na][1];
            acc[na][2] = (iq1 || ik0) ? -1e9f : acc[na][2];
            acc[na][3] = (iq1 || ik1) ? -1e9f : acc[na][3];
            mx0 = fmaxf(mx0, fmaxf(acc[na][0], acc[na][1]));
            mx1 = fmaxf(mx1, fmaxf(acc[na][2], acc[na][3]));
        }
        mx0 = fmaxf(mx0, __shfl_xor_sync(FULL, mx0, 1));
        mx0 = fmaxf(mx0, __shfl_xor_sync(FULL, mx0, 2));
        mx1 = fmaxf(mx1, __shfl_xor_sync(FULL, mx1, 1));
        mx1 = fmaxf(mx1, __shfl_xor_sync(FULL, mx1, 2));
        if (t == 0) {
            Mred[rr04 + kspl]       = mx0;   // per-warp max; consumed at combine
            Mred[rr04 + 32 + kspl]  = mx1;   // (rr0+8)*4
        }

        // ---- exp2 in fp16 pairs (against OWN warp max) -> P fragments ----
        uint32_t ph[16][2];
#pragma unroll
        for (int na = 0; na < 16; na++) {
            ph[na][0] = h2exp2(pack_h2(acc[na][0] - mx0, acc[na][1] - mx0));
            ph[na][1] = h2exp2(pack_h2(acc[na][2] - mx1, acc[na][3] - mx1));
        }

        // ---- phase 3: O_partial = P @ V  +  row sums via ones-column mma ----
        float oacc[4][4];
#pragma unroll
        for (int na = 0; na < 4; na++)
#pragma unroll
            for (int q = 0; q < 4; q++) oacc[na][q] = 0.f;
        float osum[4] = {0.f, 0.f, 0.f, 0.f};

#pragma unroll
        for (int j = 0; j < 8; j++) {
            const uint32_t pa[4] = { ph[2*j][0], ph[2*j][1], ph[2*j+1][0], ph[2*j+1][1] };
            const int kk = kb0 + 16*j + 2*t;
#pragma unroll
            for (int na = 0; na < 4; na++) {
                const __half* bb = Vth + (na*8 + g)*VT_STR + kk;
                uint32_t bf[2] = { *(const uint32_t*)bb, *(const uint32_t*)(bb + 8) };
                mma_f16(oacc[na], pa, bf);
            }
            mma_f16(osum, pa, onesbf);     // col 0 accumulates row sum
        }
        if (t == 0) {                       // lane t=0 holds col 0 = exact row sum
            Sred[rr04 + kspl]      = osum[0];
            Sred[rr04 + 32 + kspl] = osum[2];
        }

        // ---- store partials ----
        {
            float* op = Op + warp * 640;
#pragma unroll
            for (int na = 0; na < 4; na++) {
                const int c = na*8 + 2*t;
                *(float2*)&op[g*40 + c]     = make_float2(oacc[na][0], oacc[na][1]);
                *(float2*)&op[(g+8)*40 + c] = make_float2(oacc[na][2], oacc[na][3]);
            }
        }
        __syncthreads();

        // ---- combine 4 key-split partials with per-warp-max rescale ----
        {
            const int r  = tid >> 3;            // 0..63
            const int c4 = (tid & 7) * 4;       // 0..28
            const int wb = (r >> 4) * 4;        // ma*4
            const int rl = r & 15;
            const float4 m4 = *(float4*)&Mred[r*4];
            const float M = fmaxf(fmaxf(m4.x, m4.y), fmaxf(m4.z, m4.w));
            const float sc0 = ex2f(m4.x - M);
            const float sc1 = ex2f(m4.y - M);
            const float sc2 = ex2f(m4.z - M);
            const float sc3 = ex2f(m4.w - M);
            const float4 s4 = *(float4*)&Sred[r*4];
            const float sum = s4.x*sc0 + s4.y*sc1 + s4.z*sc2 + s4.w*sc3;

            float4 o = {0.f, 0.f, 0.f, 0.f};
            const float scs[4] = {sc0, sc1, sc2, sc3};
#pragma unroll
            for (int ks = 0; ks < 4; ks++) {
                const float4 p = *(float4*)&Op[(wb + ks)*640 + rl*40 + c4];
                o.x += p.x * scs[ks];
                o.y += p.y * scs[ks];
                o.z += p.z * scs[ks];
                o.w += p.w * scs[ks];
            }
            const float rs = 1.0f / sum;
            uint2 ov;
            ov.x = pack_h2(o.x*rs, o.y*rs);
            ov.y = pack_h2(o.z*rs, o.w*rs);
            *(uint2*)&Ogh[(size_t)(q0 + r)*D_ + c4] = ov;
        }
    }
}

// ---------------- launcher --------------------------------------------------
extern "C" void kernel_launch(void* const* d_in, const int* in_sizes, int n_in,
                              void* d_out, int out_size) {
    const float* h    = (const float*)d_in[0];
    const int*   mask = (const int*)  d_in[1];
    const int*   nc   = (const int*)  d_in[2];
    const float* Wq   = (const float*)d_in[3];
    const float* bq   = (const float*)d_in[4];
    const float* Wk   = (const float*)d_in[5];
    const float* bk   = (const float*)d_in[6];
    const float* Wv   = (const float*)d_in[7];
    const float* bv   = (const float*)d_in[8];
    const float* Wo   = (const float*)d_in[9];
    const float* bo   = (const float*)d_in[10];
    float* out = (float*)d_out;

    cudaFuncSetAttribute(attn_kernel, cudaFuncAttributeMaxDynamicSharedMemorySize,
                         ATTN_SMEM_BYTES);
    cudaFuncSetAttribute(qkv_kernel, cudaFuncAttributeMaxDynamicSharedMemorySize,
                         GEMMH_SMEM_BYTES);
    cudaFuncSetAttribute(oproj_kernel, cudaFuncAttributeMaxDynamicSharedMemorySize,
                         GEMMH_SMEM_BYTES);

    mask_kernel<<<M_/256, 256>>>(mask, nc);
    convh_kernel<<<M_*D_/1024, 256>>>(h);
    convw_kernel<<<256, 256>>>(Wq, Wk, Wv, Wo);
    qkv_kernel<<<dim3(M_/128, 1, 3), 256, GEMMH_SMEM_BYTES>>>(bq, bk, bv);
    attn_kernel<<<B_*H_*2, 512, ATTN_SMEM_BYTES>>>();
    oproj_kernel<<<dim3(M_/128, 1, 1), 256, GEMMH_SMEM_BYTES>>>(bo, h, out);
}

// round 17
// speedup vs baseline: 1.0431x; 1.0431x over previous
#include <cuda_runtime.h>
#include <cuda_fp16.h>
#include <math.h>
#include <stdint.h>

#define B_  64
#define N_  512
#define D_  256
#define H_  8
#define DK_ 32
#define M_  (B_*N_)   // 32768

// Q pre-scale: (1/sqrt(DK)) * log2(e)  -> softmax done in exp2 domain
#define QSCALE 0.25502421277695494f

// ---------------- scratch (static device globals; no allocation) ----------
__device__ __align__(256) __half g_hh[M_*D_];     // h in fp16
__device__ __align__(256) __half g_qh[M_*D_];
__device__ __align__(256) __half g_kh[M_*D_];
__device__ __align__(256) __half g_vh[M_*D_];
__device__ __align__(256) __half g_aoh[M_*D_];    // attention output fp16
__device__ __align__(256) __half g_wt[4*D_*D_];   // fp16 W^T (n-major) x4
__device__ unsigned char g_inv[M_];
__device__ unsigned int  g_invbits[M_/32];

// ---------------- helpers ---------------------------------------------------
__device__ __forceinline__ uint32_t pack_h2(float lo, float hi) {
    uint32_t r;
    asm("cvt.rn.f16x2.f32 %0, %1, %2;" : "=r"(r) : "f"(hi), "f"(lo));
    return r;
}
__device__ __forceinline__ float ex2f(float x) {
    float r;
    asm("ex2.approx.f32 %0, %1;" : "=f"(r) : "f"(x));
    return r;
}
__device__ __forceinline__ uint32_t h2exp2(uint32_t x) {
    uint32_t r;
    asm("ex2.approx.f16x2 %0, %1;" : "=r"(r) : "r"(x));
    return r;
}
__device__ __forceinline__ void mma_f16(float* d, const uint32_t* a, const uint32_t* b) {
    asm volatile(
        "mma.sync.aligned.m16n8k16.row.col.f32.f16.f16.f32 "
        "{%0,%1,%2,%3}, {%4,%5,%6,%7}, {%8,%9}, {%0,%1,%2,%3};\n"
        : "+f"(d[0]), "+f"(d[1]), "+f"(d[2]), "+f"(d[3])
        : "r"(a[0]), "r"(a[1]), "r"(a[2]), "r"(a[3]), "r"(b[0]), "r"(b[1]));
}
__device__ __forceinline__ void ldsm_x4(uint32_t& r0, uint32_t& r1, uint32_t& r2,
                                        uint32_t& r3, uint32_t saddr) {
    asm volatile("ldmatrix.sync.aligned.m8n8.x4.shared.b16 {%0,%1,%2,%3}, [%4];"
                 : "=r"(r0), "=r"(r1), "=r"(r2), "=r"(r3) : "r"(saddr));
}
__device__ __forceinline__ void cpasync16(void* smem_dst, const void* gptr) {
    uint32_t d = (uint32_t)__cvta_generic_to_shared(smem_dst);
    asm volatile("cp.async.ca.shared.global [%0], [%1], 16;\n" :: "r"(d), "l"(gptr));
}

// ---------------- prep kernels ----------------------------------------------
__global__ void mask_kernel(const int* __restrict__ mask,
                            const int* __restrict__ ncount) {
    const int idx = blockIdx.x * 256 + threadIdx.x;
    if (idx < M_) {
        const int b = idx >> 9;
        const int n = idx & 511;
        const bool inv = (mask[2*idx] != 0) || (mask[2*idx+1] != 0) || (n >= ncount[b]);
        g_inv[idx] = inv ? 1 : 0;
        const unsigned bal = __ballot_sync(0xffffffffu, inv);
        if ((threadIdx.x & 31) == 0) g_invbits[idx >> 5] = bal;
    }
}

// h (f32) -> g_hh (fp16); one float4 per thread
__global__ void convh_kernel(const float* __restrict__ h) {
    const int idx = blockIdx.x * 256 + threadIdx.x;   // 0 .. M_*D_/4-1
    const float4 v = *(const float4*)&h[idx * 4];
    uint2 o;
    o.x = pack_h2(v.x, v.y);
    o.y = pack_h2(v.z, v.w);
    *(uint2*)&g_hh[idx * 4] = o;
}

// W (f32 [k][n]) -> g_wt (fp16 W^T [n][k]); 4 k-entries per thread
__global__ void convw_kernel(const float* __restrict__ Wq, const float* __restrict__ Wk,
                             const float* __restrict__ Wv, const float* __restrict__ Wo) {
    const int idx = blockIdx.x * 256 + threadIdx.x;   // 65536 threads
    const int m = idx >> 14;                          // matrix 0..3
    const int r = idx & 16383;
    const int n = r & 255;
    const int k0 = (r >> 8) * 4;
    const float* src = (m == 0) ? Wq : (m == 1) ? Wk : (m == 2) ? Wv : Wo;
    uint2 o;
    o.x = pack_h2(src[(k0+0)*D_ + n], src[(k0+1)*D_ + n]);
    o.y = pack_h2(src[(k0+2)*D_ + n], src[(k0+3)*D_ + n]);
    *(uint2*)&g_wt[m*D_*D_ + n*D_ + k0] = o;
}

// ---------------- fused QKV: A resident in smem, W streamed ------------------
// 256 blocks (1 per 128-row strip of h), 256 thr / 8 warps (4m x 2n, 32x64).
// A: [8 chunks][128 rows][40h] resident (81920 B). W ring: 3 x 10240 B.
// 48 W-tiles: idx = z*16 + nn*8 + kk  (z in 0..2, nn n-half, kk k-chunk).
#define QKV_A_B    81920
#define QKV_WST_B  10240
#define QKV_SMEM_BYTES (QKV_A_B + 3*QKV_WST_B)   // 112640

__global__ void __launch_bounds__(256, 2)
qkv_fused_kernel(const float* __restrict__ bq, const float* __restrict__ bk,
                 const float* __restrict__ bv) {
    extern __shared__ char smc[];
    const uint32_t sb = (uint32_t)__cvta_generic_to_shared(smc);

    const int tid  = threadIdx.x;
    const int lane = tid & 31, warp = tid >> 5;
    const int g = lane >> 2, t = lane & 3;
    const int lrow = lane & 7, grp = lane >> 3;
    const int mw = (warp >> 1) * 32, nw = (warp & 1) * 64;
    const int row0 = blockIdx.x * 128;

    const int ar = tid >> 2, ac = (tid & 3) * 8;    // loader lanes

    // ---- load A strip (128 x 256) into 8 resident chunks ----
    {
        const __half* gA = g_hh + (size_t)(row0 + ar)*D_ + ac;
#pragma unroll
        for (int c = 0; c < 8; c++) {
            __half* Ach = (__half*)(smc + c*QKV_WST_B);
#pragma unroll
            for (int p = 0; p < 2; p++)
                cpasync16(&Ach[(ar + 64*p)*40 + ac],
                          gA + (size_t)(64*p)*D_ + c*32);
        }
        asm volatile("cp.async.commit_group;\n" ::: "memory");
    }

    auto issueW = [&](int idx, int stage) {
        const int z  = idx >> 4;
        const int nn = (idx >> 3) & 1;
        const int kk = idx & 7;
        __half* Ws = (__half*)(smc + QKV_A_B + stage*QKV_WST_B);
        const __half* gW = g_wt + (size_t)z*D_*D_
                         + (size_t)(nn*128 + ar)*D_ + kk*32 + ac;
#pragma unroll
        for (int p = 0; p < 2; p++)
            cpasync16(&Ws[(ar + 64*p)*40 + ac], gW + (size_t)(64*p)*D_);
        asm volatile("cp.async.commit_group;\n" ::: "memory");
    };

    issueW(0, 0);    // group 1
    issueW(1, 1);    // group 2

    const uint32_t a_off = (uint32_t)(((mw + (grp&1)*8 + lrow)*40 + (grp>>1)*8) * 2);
    const uint32_t b_off = (uint32_t)(((nw + (grp>>1)*8 + lrow)*40 + (grp&1)*8) * 2);

    float acc[2][8][4];

    for (int i = 0; i < 48; i++) {
        if (i < 47) asm volatile("cp.async.wait_group 1;\n" ::: "memory");
        else        asm volatile("cp.async.wait_group 0;\n" ::: "memory");
        __syncthreads();
        if (i < 46) issueW(i + 2, (i + 2) % 3);

        const int kc = i & 7;
        if (kc == 0) {
#pragma unroll
            for (int m2 = 0; m2 < 2; m2++)
#pragma unroll
                for (int j = 0; j < 8; j++)
#pragma unroll
                    for (int q = 0; q < 4; q++) acc[m2][j][q] = 0.f;
        }

        const int ring = i % 3;
        const uint32_t a_base = sb + (uint32_t)(kc*QKV_WST_B) + a_off;
        const uint32_t b_base = sb + (uint32_t)(QKV_A_B + ring*QKV_WST_B) + b_off;
#pragma unroll
        for (int kh = 0; kh < 2; kh++) {
            uint32_t aq[2][4];
            ldsm_x4(aq[0][0], aq[0][1], aq[0][2], aq[0][3], a_base + kh*32);
            ldsm_x4(aq[1][0], aq[1][1], aq[1][2], aq[1][3], a_base + 1280 + kh*32);
#pragma unroll
            for (int nb = 0; nb < 4; nb++) {
                uint32_t bf[4];
                ldsm_x4(bf[0], bf[1], bf[2], bf[3], b_base + nb*1280 + kh*32);
                mma_f16(acc[0][nb*2+0], aq[0], bf);
                mma_f16(acc[0][nb*2+1], aq[0], bf + 2);
                mma_f16(acc[1][nb*2+0], aq[1], bf);
                mma_f16(acc[1][nb*2+1], aq[1], bf + 2);
            }
        }
        __syncthreads();

        if (kc == 7) {
            const int zz = i >> 4;
            const int nn = (i >> 3) & 1;
            const float* bvec = (zz == 0) ? bq : (zz == 1) ? bk : bv;
            __half* dst      = (zz == 0) ? g_qh : (zz == 1) ? g_kh : g_vh;
            const float scale = (zz == 0) ? QSCALE : 1.0f;
#pragma unroll
            for (int m2 = 0; m2 < 2; m2++) {
                const int r0g = row0 + mw + m2*16 + g;
#pragma unroll
                for (int na = 0; na < 8; na++) {
                    const int c0 = nn*128 + nw + na*8 + 2*t;
                    *(uint32_t*)&dst[(size_t)r0g*D_ + c0] =
                        pack_h2((acc[m2][na][0] + bvec[c0])*scale,
                                (acc[m2][na][1] + bvec[c0+1])*scale);
                    *(uint32_t*)&dst[(size_t)(r0g+8)*D_ + c0] =
                        pack_h2((acc[m2][na][2] + bvec[c0])*scale,
                                (acc[m2][na][3] + bvec[c0+1])*scale);
                }
            }
        }
    }
}

// ---------------- fp16 mma GEMM (R14-validated, used by oproj) ---------------
#define HSTAGE_B 20480            // bytes per stage: (128*40 + 128*40) halves
#define GEMMH_SMEM_BYTES (3*HSTAGE_B)   // 61440

__global__ void __launch_bounds__(256)
oproj_kernel(const float* __restrict__ bo,
             const float* __restrict__ hres, float* __restrict__ out) {
    extern __shared__ char smc[];
    const uint32_t sb = (uint32_t)__cvta_generic_to_shared(smc);

    const int tid  = threadIdx.x;
    const int lane = tid & 31, warp = tid >> 5;
    const int g = lane >> 2, t = lane & 3;
    const int lrow = lane & 7, grp = lane >> 3;
    const int mw = (warp >> 1) * 32, nw = (warp & 1) * 64;
    const int row0 = blockIdx.x * 128, col0 = blockIdx.y * 128;

    const int ar = tid >> 2, ac = (tid & 3) * 8;

    float acc[2][8][4];
#pragma unroll
    for (int i = 0; i < 2; i++)
#pragma unroll
        for (int j = 0; j < 8; j++)
#pragma unroll
            for (int q = 0; q < 4; q++) acc[i][j][q] = 0.f;

    const __half* gA = g_aoh + (size_t)(row0 + ar)*D_ + ac;
    const __half* gB = g_wt + 3*D_*D_ + (size_t)(col0 + ar)*D_ + ac;

    auto issue = [&](int chunk, int stage) {
        __half* As = (__half*)(smc + stage*HSTAGE_B);
        __half* Bs = As + 5120;
#pragma unroll
        for (int p = 0; p < 2; p++) {
            cpasync16(&As[(ar + 64*p)*40 + ac], gA + (size_t)(64*p)*D_ + chunk*32);
            cpasync16(&Bs[(ar + 64*p)*40 + ac], gB + (size_t)(64*p)*D_ + chunk*32);
        }
        asm volatile("cp.async.commit_group;\n" ::: "memory");
    };

    issue(0, 0);
    issue(1, 1);

    const uint32_t a_base = sb
        + (uint32_t)(((mw + (grp&1)*8 + lrow)*40 + (grp>>1)*8) * 2);
    const uint32_t b_base = sb + 10240
        + (uint32_t)(((nw + (grp>>1)*8 + lrow)*40 + (grp&1)*8) * 2);

    for (int i = 0; i < 8; i++) {
        if (i < 7) asm volatile("cp.async.wait_group 1;\n" ::: "memory");
        else       asm volatile("cp.async.wait_group 0;\n" ::: "memory");
        __syncthreads();
        if (i < 6) issue(i + 2, (i + 2) % 3);

        const uint32_t st = (uint32_t)((i % 3) * HSTAGE_B);
#pragma unroll
        for (int kh = 0; kh < 2; kh++) {
            uint32_t aq[2][4];
            ldsm_x4(aq[0][0], aq[0][1], aq[0][2], aq[0][3],
                    a_base + st + kh*32);
            ldsm_x4(aq[1][0], aq[1][1], aq[1][2], aq[1][3],
                    a_base + st + 1280 + kh*32);
#pragma unroll
            for (int nb = 0; nb < 4; nb++) {
                uint32_t bf[4];
                ldsm_x4(bf[0], bf[1], bf[2], bf[3],
                        b_base + st + nb*1280 + kh*32);
                mma_f16(acc[0][nb*2+0], aq[0], bf);
                mma_f16(acc[0][nb*2+1], aq[0], bf + 2);
                mma_f16(acc[1][nb*2+0], aq[1], bf);
                mma_f16(acc[1][nb*2+1], aq[1], bf + 2);
            }
        }
        __syncthreads();
    }

#pragma unroll
    for (int ma = 0; ma < 2; ma++) {
        const int r0g = row0 + mw + ma*16 + g;
#pragma unroll
        for (int na = 0; na < 8; na++) {
            const int c0 = col0 + nw + na*8 + 2*t;
            float2 o0, o1;
            o0.x = acc[ma][na][0] + bo[c0];
            o0.y = acc[ma][na][1] + bo[c0+1];
            o1.x = acc[ma][na][2] + bo[c0];
            o1.y = acc[ma][na][3] + bo[c0+1];
            const float2 ra = *(const float2*)&hres[(size_t)r0g*D_ + c0];
            const float2 rb = *(const float2*)&hres[(size_t)(r0g+8)*D_ + c0];
            o0.x += ra.x; o0.y += ra.y;
            o1.x += rb.x; o1.y += rb.y;
            *(float2*)&out[(size_t)r0g*D_ + c0]     = o0;
            *(float2*)&out[(size_t)(r0g+8)*D_ + c0] = o1;
        }
    }
}

// ---------------- register-flash attention (validated R14) -------------------
#define KH_STR  40                // halves per K/Q smem row (80 B, cf-free ldsm)
#define VT_STR  520               // halves per dk row of V^T
#define OFFB_K  0                 // Kh[512][40]h  = 40960 B
#define OFFB_VT 40960             // Vt[32][520]h  = 33280 B
#define OFFB_Q  74240             // Qh[64][40]h   = 5120 B
#define OFFB_OP 79360             // Op[16][16][40]f = 40960 B
#define OFFB_MR 120320            // Mred[64][4]f (per-warp maxes)
#define OFFB_SR 121344            // Sred[64][4]f (per-warp sums)
#define ATTN_SMEM_BYTES 122368

__global__ void __launch_bounds__(512)
attn_kernel() {
    extern __shared__ char smc[];
    __half* Qhs  = (__half*)(smc + OFFB_Q);
    __half* Khs  = (__half*)(smc + OFFB_K);
    __half* Vth  = (__half*)(smc + OFFB_VT);
    float*  Op   = (float*) (smc + OFFB_OP);
    float*  Mred = (float*) (smc + OFFB_MR);
    float*  Sred = (float*) (smc + OFFB_SR);
    const uint32_t sb = (uint32_t)__cvta_generic_to_shared(smc);

    const int tid  = threadIdx.x;
    const int lane = tid & 31;
    const int warp = tid >> 5;
    const int g = lane >> 2, t = lane & 3;
    const int lrow = lane & 7, grp = lane >> 3;
    const int ma   = warp >> 2;          // q-row atom 0..3
    const int kspl = warp & 3;           // key-split 0..3
    const int bh   = blockIdx.x >> 1;
    const int half = blockIdx.x & 1;
    const int b  = bh >> 3;
    const int hh = bh & 7;

    const __half* Qg  = g_qh  + (size_t)b*N_*D_ + hh*DK_;
    const __half* Kg  = g_kh  + (size_t)b*N_*D_ + hh*DK_;
    const __half* Vg  = g_vh  + (size_t)b*N_*D_ + hh*DK_;
    __half*       Ogh = g_aoh + (size_t)b*N_*D_ + hh*DK_;

    uint32_t invw[4];
#pragma unroll
    for (int j = 0; j < 4; j++)
        invw[j] = g_invbits[b*16 + kspl*4 + j] >> (t << 1);

    // ---- load K (fp16 row-major) and V (fp16 transposed) ----
    {
        const int r = tid >> 3, cg = (tid & 7) * 4;
#pragma unroll
        for (int p = 0; p < 8; p++) {
            const int key = r + 64*p;
            *(uint2*)&Khs[key*KH_STR + cg] = *(const uint2*)&Kg[(size_t)key*D_ + cg];
            const uint2 u = *(const uint2*)&Vg[(size_t)key*D_ + cg];
            const __half2 v01 = *reinterpret_cast<const __half2*>(&u.x);
            const __half2 v23 = *reinterpret_cast<const __half2*>(&u.y);
            Vth[(cg+0)*VT_STR + key] = __low2half(v01);
            Vth[(cg+1)*VT_STR + key] = __high2half(v01);
            Vth[(cg+2)*VT_STR + key] = __low2half(v23);
            Vth[(cg+3)*VT_STR + key] = __high2half(v23);
        }
    }

    const int kb0 = kspl * 128;
    const int rr0 = ma*16 + g;
    const int rr04 = rr0 * 4;
    const uint32_t FULL = 0xffffffffu;
    const uint32_t onesf = (g == 0) ? 0x3C003C00u : 0u;
    const uint32_t onesbf[2] = { onesf, onesf };

    const uint32_t qa_base = sb + OFFB_Q
        + (uint32_t)(((ma*16 + (grp&1)*8 + lrow)*KH_STR + (grp>>1)*8) * 2);
    const uint32_t ka_row  = (uint32_t)((grp>>1)*8 + lrow);
    const uint32_t ka_koff = (uint32_t)((grp&1)*8);

    for (int qt = 0; qt < 4; qt++) {
        const int q0 = half*256 + qt*64;

        __syncthreads();
        {
            const int r = tid >> 3, cg = (tid & 7) * 4;
            *(uint2*)&Qhs[r*KH_STR + cg] = *(const uint2*)&Qg[(size_t)(q0 + r)*D_ + cg];
        }
        __syncthreads();

        const bool iq0 = g_inv[b*N_ + q0 + rr0]     != 0;
        const bool iq1 = g_inv[b*N_ + q0 + rr0 + 8] != 0;

        // ---- phase 1: S = Q @ K^T ----
        uint32_t aq[2][4];
        ldsm_x4(aq[0][0], aq[0][1], aq[0][2], aq[0][3], qa_base);
        ldsm_x4(aq[1][0], aq[1][1], aq[1][2], aq[1][3], qa_base + 32);

        float acc[16][4];
#pragma unroll
        for (int j = 0; j < 8; j++) {
            const uint32_t kaddr = sb + OFFB_K
                + (uint32_t)((((kb0 + j*16) + ka_row)*KH_STR + ka_koff) * 2);
            uint32_t kb[4], kc[4];
            ldsm_x4(kb[0], kb[1], kb[2], kb[3], kaddr);
            ldsm_x4(kc[0], kc[1], kc[2], kc[3], kaddr + 32);
            acc[2*j][0] = acc[2*j][1] = acc[2*j][2] = acc[2*j][3] = 0.f;
            acc[2*j+1][0] = acc[2*j+1][1] = acc[2*j+1][2] = acc[2*j+1][3] = 0.f;
            mma_f16(acc[2*j],   aq[0], kb);
            mma_f16(acc[2*j],   aq[1], kc);
            mma_f16(acc[2*j+1], aq[0], kb + 2);
            mma_f16(acc[2*j+1], aq[1], kc + 2);
        }

        // ---- mask + per-warp row max ----
        float mx0 = -1e30f, mx1 = -1e30f;
#pragma unroll
        for (int na = 0; na < 16; na++) {
            const uint32_t w = invw[na >> 2] >> ((na & 3) << 3);
            const bool ik0 = (w & 1u) != 0;
            const bool ik1 = (w & 2u) != 0;
            acc[na][0] = (iq0 || ik0) ? -1e9f : acc[na][0];
            acc[na][1] = (iq0 || ik1) ? -1e9f : acc[na][1];
            acc[na][2] = (iq1 || ik0) ? -1e9f : acc[na][2];
            acc[na][3] = (iq1 || ik1) ? -1e9f : acc[na][3];
            mx0 = fmaxf(mx0, fmaxf(acc[na][0], acc[na][1]));
            mx1 = fmaxf(mx1, fmaxf(acc[na][2], acc[na][3]));
        }
        mx0 = fmaxf(mx0, __shfl_xor_sync(FULL, mx0, 1));
        mx0 = fmaxf(mx0, __shfl_xor_sync(FULL, mx0, 2));
        mx1 = fmaxf(mx1, __shfl_xor_sync(FULL, mx1, 1));
        mx1 = fmaxf(mx1, __shfl_xor_sync(FULL, mx1, 2));
        if (t == 0) {
            Mred[rr04 + kspl]       = mx0;
            Mred[rr04 + 32 + kspl]  = mx1;
        }

        // ---- exp2 (own warp max) -> P fragments ----
        uint32_t ph[16][2];
#pragma unroll
        for (int na = 0; na < 16; na++) {
            ph[na][0] = h2exp2(pack_h2(acc[na][0] - mx0, acc[na][1] - mx0));
            ph[na][1] = h2exp2(pack_h2(acc[na][2] - mx1, acc[na][3] - mx1));
        }

        // ---- phase 3: P @ V + ones-column row sums ----
        float oacc[4][4];
#pragma unroll
        for (int na = 0; na < 4; na++)
#pragma unroll
            for (int q = 0; q < 4; q++) oacc[na][q] = 0.f;
        float osum[4] = {0.f, 0.f, 0.f, 0.f};

#pragma unroll
        for (int j = 0; j < 8; j++) {
            const uint32_t pa[4] = { ph[2*j][0], ph[2*j][1], ph[2*j+1][0], ph[2*j+1][1] };
            const int kk = kb0 + 16*j + 2*t;
#pragma unroll
            for (int na = 0; na < 4; na++) {
                const __half* bb = Vth + (na*8 + g)*VT_STR + kk;
                uint32_t bf[2] = { *(const uint32_t*)bb, *(const uint32_t*)(bb + 8) };
                mma_f16(oacc[na], pa, bf);
            }
            mma_f16(osum, pa, onesbf);
        }
        if (t == 0) {
            Sred[rr04 + kspl]      = osum[0];
            Sred[rr04 + 32 + kspl] = osum[2];
        }

        // ---- store partials ----
        {
            float* op = Op + warp * 640;
#pragma unroll
            for (int na = 0; na < 4; na++) {
                const int c = na*8 + 2*t;
                *(float2*)&op[g*40 + c]     = make_float2(oacc[na][0], oacc[na][1]);
                *(float2*)&op[(g+8)*40 + c] = make_float2(oacc[na][2], oacc[na][3]);
            }
        }
        __syncthreads();

        // ---- combine with per-warp-max rescale ----
        {
            const int r  = tid >> 3;
            const int c4 = (tid & 7) * 4;
            const int wb = (r >> 4) * 4;
            const int rl = r & 15;
            const float4 m4 = *(float4*)&Mred[r*4];
            const float M = fmaxf(fmaxf(m4.x, m4.y), fmaxf(m4.z, m4.w));
            const float sc0 = ex2f(m4.x - M);
            const float sc1 = ex2f(m4.y - M);
            const float sc2 = ex2f(m4.z - M);
            const float sc3 = ex2f(m4.w - M);
            const float4 s4 = *(float4*)&Sred[r*4];
            const float sum = s4.x*sc0 + s4.y*sc1 + s4.z*sc2 + s4.w*sc3;

            float4 o = {0.f, 0.f, 0.f, 0.f};
            const float scs[4] = {sc0, sc1, sc2, sc3};
#pragma unroll
            for (int ks = 0; ks < 4; ks++) {
                const float4 p = *(float4*)&Op[(wb + ks)*640 + rl*40 + c4];
                o.x += p.x * scs[ks];
                o.y += p.y * scs[ks];
                o.z += p.z * scs[ks];
                o.w += p.w * scs[ks];
            }
            const float rs = 1.0f / sum;
            uint2 ov;
            ov.x = pack_h2(o.x*rs, o.y*rs);
            ov.y = pack_h2(o.z*rs, o.w*rs);
            *(uint2*)&Ogh[(size_t)(q0 + r)*D_ + c4] = ov;
        }
    }
}

// ---------------- launcher --------------------------------------------------
extern "C" void kernel_launch(void* const* d_in, const int* in_sizes, int n_in,
                              void* d_out, int out_size) {
    const float* h    = (const float*)d_in[0];
    const int*   mask = (const int*)  d_in[1];
    const int*   nc   = (const int*)  d_in[2];
    const float* Wq   = (const float*)d_in[3];
    const float* bq   = (const float*)d_in[4];
    const float* Wk   = (const float*)d_in[5];
    const float* bk   = (const float*)d_in[6];
    const float* Wv   = (const float*)d_in[7];
    const float* bv   = (const float*)d_in[8];
    const float* Wo   = (const float*)d_in[9];
    const float* bo   = (const float*)d_in[10];
    float* out = (float*)d_out;

    cudaFuncSetAttribute(attn_kernel, cudaFuncAttributeMaxDynamicSharedMemorySize,
                         ATTN_SMEM_BYTES);
    cudaFuncSetAttribute(qkv_fused_kernel, cudaFuncAttributeMaxDynamicSharedMemorySize,
                         QKV_SMEM_BYTES);
    cudaFuncSetAttribute(oproj_kernel, cudaFuncAttributeMaxDynamicSharedMemorySize,
                         GEMMH_SMEM_BYTES);

    mask_kernel<<<M_/256, 256>>>(mask, nc);
    convh_kernel<<<M_*D_/1024, 256>>>(h);
    convw_kernel<<<256, 256>>>(Wq, Wk, Wv, Wo);
    qkv_fused_kernel<<<M_/128, 256, QKV_SMEM_BYTES>>>(bq, bk, bv);
    attn_kernel<<<B_*H_*2, 512, ATTN_SMEM_BYTES>>>();
    oproj_kernel<<<dim3(M_/128, D_/128), 256, GEMMH_SMEM_BYTES>>>(bo, h, out);
}